// round 4
// baseline (speedup 1.0000x reference)
#include <cuda_runtime.h>
#include <cstdint>

#define NB 16
#define NC 96
#define NHW 16384
#define NG 4
#define NCG 24
#define NT 256
#define EPSF 1e-5f

// ---------------- scratch (no allocations allowed -> device globals) ----------
__device__ float g_u[NB * NC * NHW];          // conv outputs (reused conv1/conv2)
__device__ float g_h[NB * NC * NHW];          // residual h (post FiLM)
__device__ float g_ao[NB * NC * NHW];         // attention output accumulator (x1+x2)
__device__ float g_qkv[NB * 3 * NC * NHW];    // shared QKV tensor (both attn paths)
__device__ float g_film[NB * 2 * NC];         // silu(t_emb @ wt^T + bt)
__device__ float g_part1[NB * NG * 64 * 2];   // conv GN partials (reused)
__device__ float g_part2[NB * NG * 96 * 2];   // GN2 partials
__device__ float g_stats1[NB * NG * 2];       // (mean, rstd)
__device__ float g_stats2[NB * NG * 2];
__device__ float g_stats3[NB * NG * 2];

__device__ __forceinline__ float silu_f(float x) { return x / (1.f + __expf(-x)); }

// ---------------- K0: FiLM MLP ------------------------------------------------
__global__ void film_kernel(const float* __restrict__ te, const float* __restrict__ wt,
                            const float* __restrict__ bt) {
    int b = blockIdx.x, o = threadIdx.x;  // 16 x 192
    const float4* e4 = (const float4*)(te + b * NT);
    const float4* w4 = (const float4*)(wt + o * NT);
    float s = bt[o];
#pragma unroll 8
    for (int k = 0; k < NT / 4; k++) {
        float4 a = e4[k], w = w4[k];
        s = fmaf(a.x, w.x, s); s = fmaf(a.y, w.y, s);
        s = fmaf(a.z, w.z, s); s = fmaf(a.w, w.w, s);
    }
    g_film[b * 192 + o] = silu_f(s);
}

// ---------------- conv3x3 (zero pad 1) + per-block GN partials ----------------
// grid: (64 row-tiles of 2 rows, 4 groups, 16 batch); block 192.
// Thread map (bank-conflict-free): co = tid % 24 (broadcast groups),
// pxg = tid / 24; pr = pxg&1 (row), pc0 = (pxg>>1)*32 (col group).
// Adjacent pxg differ by +-2 banks in s_in (row stride 130 == 2 mod 32).
// SRC==0: input = src. SRC==1: input = g_h + 0.5*g_ao (fused residual+attn add)
template <int SRC>
__global__ __launch_bounds__(192) void conv3x3_kernel(const float* __restrict__ src,
                                                      const float* __restrict__ wgt,
                                                      const float* __restrict__ bias) {
    __shared__ float s_in[8][4][130];
    __shared__ float s_w[24][73];   // stride 73: 9*co mod 32 injective -> conflict-free
    __shared__ float2 s_warp[6];
    int rt = blockIdx.x, g = blockIdx.y, b = blockIdx.z;
    int tid = threadIdx.x;
    int co = tid % 24;
    int pxg = tid / 24;
    int pr = pxg & 1, pc0 = (pxg >> 1) << 5;
    int r0 = rt << 1;
    int cog = g * NCG + co;

    float acc[32];
#pragma unroll
    for (int j = 0; j < 32; j++) acc[j] = 0.f;

    const float* srcB = (SRC == 0) ? (src + b * NC * NHW) : (g_h + b * NC * NHW);
    const float* aoB = g_ao + b * NC * NHW;

    for (int cc = 0; cc < 12; cc++) {
        int ci0 = cc << 3;
        for (int e = tid; e < 8 * 4 * 130; e += 192) {
            int ci = e / 520;
            int rem = e - ci * 520;
            int ry = rem / 130;
            int xx = rem - ry * 130;
            int gy = r0 - 1 + ry, gx = xx - 1;
            float v = 0.f;
            if ((unsigned)gy < 128u && (unsigned)gx < 128u) {
                int idx = (ci0 + ci) * NHW + (gy << 7) + gx;
                v = srcB[idx];
                if (SRC == 1) v = fmaf(0.5f, aoB[idx], v);
            }
            s_in[ci][ry][xx] = v;
        }
        for (int e = tid; e < 24 * 72; e += 192) {
            int c2 = e / 72;
            int rem = e - c2 * 72;   // rem = ci*9 + k
            s_w[c2][rem] = wgt[((g * NCG + c2) * NC + ci0) * 9 + rem];
        }
        __syncthreads();
#pragma unroll
        for (int ci = 0; ci < 8; ci++) {
#pragma unroll
            for (int dy = 0; dy < 3; dy++) {
                float wa = s_w[co][ci * 9 + dy * 3 + 0];
                float wb = s_w[co][ci * 9 + dy * 3 + 1];
                float wc = s_w[co][ci * 9 + dy * 3 + 2];
                const float* row = &s_in[ci][pr + dy][pc0];
                float a = row[0], bb = row[1];
#pragma unroll
                for (int j = 0; j < 32; j++) {
                    float cn = row[j + 2];
                    acc[j] = fmaf(a, wa, acc[j]);
                    acc[j] = fmaf(bb, wb, acc[j]);
                    acc[j] = fmaf(cn, wc, acc[j]);
                    a = bb; bb = cn;
                }
            }
        }
        __syncthreads();
    }

    float bs = bias[cog], s = 0.f, s2 = 0.f;
#pragma unroll
    for (int j = 0; j < 32; j++) {
        acc[j] += bs;
        s += acc[j];
        s2 = fmaf(acc[j], acc[j], s2);
    }
    float* op = g_u + (b * NC + cog) * NHW + ((r0 + pr) << 7) + pc0;
#pragma unroll
    for (int j = 0; j < 32; j += 4)
        *(float4*)(op + j) = make_float4(acc[j], acc[j + 1], acc[j + 2], acc[j + 3]);

    // warp shuffle tree + 6-entry serial: deterministic, no 192-long serial tail
#pragma unroll
    for (int off = 16; off; off >>= 1) {
        s += __shfl_xor_sync(0xffffffffu, s, off);
        s2 += __shfl_xor_sync(0xffffffffu, s2, off);
    }
    if ((tid & 31) == 0) s_warp[tid >> 5] = make_float2(s, s2);
    __syncthreads();
    if (tid == 0) {
        float a = 0.f, b2 = 0.f;
#pragma unroll
        for (int i = 0; i < 6; i++) { a += s_warp[i].x; b2 += s_warp[i].y; }
        int slot = (b * NG + g) * 64 + rt;
        g_part1[slot * 2 + 0] = a;
        g_part1[slot * 2 + 1] = b2;
    }
}

// ---------------- GN stats finalize (deterministic serial reduce) -------------
template <int WHICH>
__global__ void gn_reduce_kernel() {
    int bg = threadIdx.x;  // 64 = 16b x 4g
    const float* part = (WHICH == 2) ? g_part2 : g_part1;
    const int n = (WHICH == 2) ? 96 : 64;
    float s = 0.f, s2 = 0.f;
    for (int i = 0; i < n; i++) {
        s += part[(bg * n + i) * 2];
        s2 += part[(bg * n + i) * 2 + 1];
    }
    const float invN = 1.f / (float)(NCG * NHW);
    float mean = s * invN;
    float var = s2 * invN - mean * mean;
    if (var < 0.f) var = 0.f;
    float* st = (WHICH == 1) ? g_stats1 : (WHICH == 2) ? g_stats2 : g_stats3;
    st[bg * 2] = mean;
    st[bg * 2 + 1] = rsqrtf(var + EPSF);
}

// ---------------- K2: h = FiLM(silu(GN1(u))); accumulate GN2 partials ---------
__global__ void gn_film_kernel(const float* __restrict__ g1, const float* __restrict__ be1) {
    __shared__ float2 s_red[256];
    int bg = blockIdx.y;
    int b = bg >> 2, g = bg & 3;
    float mean = g_stats1[bg * 2], rstd = g_stats1[bg * 2 + 1];
    const float4* up = (const float4*)(g_u + (b * NC + g * NCG) * NHW);
    float4* hp = (float4*)(g_h + (b * NC + g * NCG) * NHW);
    int tid = threadIdx.x;
    float s = 0.f, s2 = 0.f;
#pragma unroll
    for (int kk = 0; kk < 4; kk++) {
        int i4 = blockIdx.x * 1024 + kk * 256 + tid;
        int c = g * NCG + (i4 >> 12);
        float gam = g1[c] * rstd;
        float bet = be1[c] - mean * gam;
        float sh = 1.f + g_film[b * 192 + c];
        float bi = g_film[b * 192 + 96 + c];
        float4 u = up[i4];
        float y0 = fmaf(silu_f(fmaf(u.x, gam, bet)), sh, bi);
        float y1 = fmaf(silu_f(fmaf(u.y, gam, bet)), sh, bi);
        float y2 = fmaf(silu_f(fmaf(u.z, gam, bet)), sh, bi);
        float y3 = fmaf(silu_f(fmaf(u.w, gam, bet)), sh, bi);
        s += y0 + y1 + y2 + y3;
        s2 = fmaf(y0, y0, s2); s2 = fmaf(y1, y1, s2);
        s2 = fmaf(y2, y2, s2); s2 = fmaf(y3, y3, s2);
        hp[i4] = make_float4(y0, y1, y2, y3);
    }
    s_red[tid] = make_float2(s, s2);
    __syncthreads();
    for (int off = 128; off > 0; off >>= 1) {
        if (tid < off) {
            s_red[tid].x += s_red[tid + off].x;
            s_red[tid].y += s_red[tid + off].y;
        }
        __syncthreads();
    }
    if (tid == 0) {
        int slot = bg * 96 + blockIdx.x;
        g_part2[slot * 2 + 0] = s_red[0].x;
        g_part2[slot * 2 + 1] = s_red[0].y;
    }
}

// ---------------- K3: qkv = W_qkv @ GN2(h), shared by both attn paths ---------
// grid: (4096 px-tiles of 64, 3 row-tiles of 96). block 256 = 16 rowg x 16 lg
// s_w padded to stride 97 -> the 2 row-groups per warp hit distinct banks.
__global__ __launch_bounds__(256) void qkv_kernel(const float* __restrict__ qw,
                                                  const float* __restrict__ qb,
                                                  const float* __restrict__ ga,
                                                  const float* __restrict__ ba) {
    extern __shared__ float sm[];
    float* s_hn = sm;           // 96 x 64
    float* s_w = sm + 6144;     // 96 x 97 (padded)
    int pxt = blockIdx.x, rt = blockIdx.y;
    int b = pxt >> 8, sp0 = (pxt & 255) << 6;
    int tid = threadIdx.x;

    for (int e = tid; e < 1536; e += 256) {  // float4 elements of 96x64
        int c = e >> 4;
        int grp = c / 24;
        float mean = g_stats2[(b * NG + grp) * 2];
        float rstd = g_stats2[(b * NG + grp) * 2 + 1];
        float gam = ga[c] * rstd;
        float bet = ba[c] - mean * gam;
        float4 v = *(const float4*)(g_h + (b * NC + c) * NHW + sp0 + ((e & 15) << 2));
        v.x = fmaf(v.x, gam, bet); v.y = fmaf(v.y, gam, bet);
        v.z = fmaf(v.z, gam, bet); v.w = fmaf(v.w, gam, bet);
        ((float4*)s_hn)[e] = v;
    }
    const float* qwB = qw + rt * 96 * 96;
    for (int e = tid; e < 9216; e += 256) {
        int row = e / 96, col = e - row * 96;
        s_w[row * 97 + col] = qwB[e];
    }
    __syncthreads();

    int lg = tid & 15, rowg = tid >> 4;
    float acc[6][4];
#pragma unroll
    for (int r = 0; r < 6; r++)
#pragma unroll
        for (int j = 0; j < 4; j++) acc[r][j] = 0.f;

#pragma unroll 4
    for (int c = 0; c < 96; c++) {
        float4 hv = ((const float4*)s_hn)[(c << 4) + lg];
#pragma unroll
        for (int rr = 0; rr < 6; rr++) {
            float wv = s_w[(rowg * 6 + rr) * 97 + c];
            acc[rr][0] = fmaf(wv, hv.x, acc[rr][0]);
            acc[rr][1] = fmaf(wv, hv.y, acc[rr][1]);
            acc[rr][2] = fmaf(wv, hv.z, acc[rr][2]);
            acc[rr][3] = fmaf(wv, hv.w, acc[rr][3]);
        }
    }
#pragma unroll
    for (int rr = 0; rr < 6; rr++) {
        int row = rt * 96 + rowg * 6 + rr;
        float bb = qb[row];
        *(float4*)(g_qkv + (b * 288 + row) * NHW + sp0 + (lg << 2)) =
            make_float4(acc[rr][0] + bb, acc[rr][1] + bb, acc[rr][2] + bb, acc[rr][3] + bb);
    }
}

// ---------------- K4: window attention (6x6 channel-attn, 16 heads) + proj ----
// block = one 8x8 window. 16 teams of 16 lanes, 4 px per lane.
// q/k/v loaded straight from global into registers (each team needs only its
// own 18 channel rows) -> no qkv smem staging, single __syncthreads.
// SHIFT=0 writes g_ao; SHIFT=4 (wraparound roll) accumulates.
template <int SHIFT, int ACC>
__global__ __launch_bounds__(256) void winattn_kernel(const float* __restrict__ pw,
                                                      const float* __restrict__ pb) {
    extern __shared__ float sm[];
    float* s_out = sm;            // 96 x 64
    float* s_pw = sm + 6144;      // 96 x 97 (padded)
    int w = blockIdx.x, b = blockIdx.y;
    int wi = w >> 4, wj = w & 15;
    int r0 = wi * 8 + SHIFT, c0 = wj * 8 + SHIFT;
    int tid = threadIdx.x;
    int team = tid >> 4, ln = tid & 15, l0 = ln << 2;

    // stage proj weights (no dependency; overlaps with global q/k/v loads)
    for (int e = tid; e < 9216; e += 256) {
        int row = e / 96, col = e - row * 96;
        s_pw[row * 97 + col] = pw[e];
    }

    // this lane's 4 pixels (one half-row of the window; never splits at wrap)
    int gr = (r0 + (l0 >> 3)) & 127;
    int gc = (c0 + (l0 & 7)) & 127;
    const float* qkvB = g_qkv + (size_t)b * 288 * NHW + (gr << 7) + gc;

    float q[6][4], k[6][4], v[6][4];
#pragma unroll
    for (int d = 0; d < 6; d++) {
        float4 t;
        t = *(const float4*)(qkvB + (team * 6 + d) * NHW);
        q[d][0] = t.x; q[d][1] = t.y; q[d][2] = t.z; q[d][3] = t.w;
        t = *(const float4*)(qkvB + (96 + team * 6 + d) * NHW);
        k[d][0] = t.x; k[d][1] = t.y; k[d][2] = t.z; k[d][3] = t.w;
        t = *(const float4*)(qkvB + (192 + team * 6 + d) * NHW);
        v[d][0] = t.x; v[d][1] = t.y; v[d][2] = t.z; v[d][3] = t.w;
    }
    float S[6][6];
#pragma unroll
    for (int d = 0; d < 6; d++)
#pragma unroll
        for (int e = 0; e < 6; e++) {
            float ps = q[d][0] * k[e][0];
            ps = fmaf(q[d][1], k[e][1], ps);
            ps = fmaf(q[d][2], k[e][2], ps);
            ps = fmaf(q[d][3], k[e][3], ps);
            S[d][e] = ps;
        }
#pragma unroll
    for (int off = 8; off > 0; off >>= 1)
#pragma unroll
        for (int d = 0; d < 6; d++)
#pragma unroll
            for (int e = 0; e < 6; e++)
                S[d][e] += __shfl_xor_sync(0xffffffffu, S[d][e], off);

    const float scl = 0.4082482904638631f;  // 6^-0.5
#pragma unroll
    for (int d = 0; d < 6; d++) {
        float m = S[d][0];
#pragma unroll
        for (int e = 1; e < 6; e++) m = fmaxf(m, S[d][e]);
        float sum = 0.f;
#pragma unroll
        for (int e = 0; e < 6; e++) {
            S[d][e] = __expf((S[d][e] - m) * scl);
            sum += S[d][e];
        }
        float inv = 1.f / sum;
        float o[4];
#pragma unroll
        for (int j = 0; j < 4; j++) {
            float t = S[d][0] * v[0][j];
            t = fmaf(S[d][1], v[1][j], t);
            t = fmaf(S[d][2], v[2][j], t);
            t = fmaf(S[d][3], v[3][j], t);
            t = fmaf(S[d][4], v[4][j], t);
            t = fmaf(S[d][5], v[5][j], t);
            o[j] = t * inv;
        }
        *(float4*)(s_out + ((team * 6 + d) << 6) + l0) =
            make_float4(o[0], o[1], o[2], o[3]);
    }
    __syncthreads();  // s_out + s_pw complete

    float pa[6][4];
#pragma unroll
    for (int m = 0; m < 6; m++)
#pragma unroll
        for (int j = 0; j < 4; j++) pa[m][j] = 0.f;
#pragma unroll 4
    for (int c = 0; c < 96; c++) {
        float4 ov = ((const float4*)s_out)[(c << 4) + ln];
#pragma unroll
        for (int m = 0; m < 6; m++) {
            float wv = s_pw[(team * 6 + m) * 97 + c];
            pa[m][0] = fmaf(wv, ov.x, pa[m][0]);
            pa[m][1] = fmaf(wv, ov.y, pa[m][1]);
            pa[m][2] = fmaf(wv, ov.z, pa[m][2]);
            pa[m][3] = fmaf(wv, ov.w, pa[m][3]);
        }
    }
    float* outp = g_ao + (size_t)b * NC * NHW + (gr << 7) + gc;
#pragma unroll
    for (int m = 0; m < 6; m++) {
        int co = team * 6 + m;
        float bb = pb[co];
        float4 val = make_float4(pa[m][0] + bb, pa[m][1] + bb, pa[m][2] + bb, pa[m][3] + bb);
        float* p = outp + co * NHW;
        if (ACC) {
            float4 old = *(float4*)p;
            val.x += old.x; val.y += old.y; val.z += old.z; val.w += old.w;
        }
        *(float4*)p = val;
    }
}

// ---------------- K6: out = silu(GN3(u)) --------------------------------------
__global__ void gn_out_kernel(const float* __restrict__ g2, const float* __restrict__ be2,
                              float* __restrict__ out) {
    int bg = blockIdx.y;
    int b = bg >> 2, g = bg & 3;
    float mean = g_stats3[bg * 2], rstd = g_stats3[bg * 2 + 1];
    const float4* up = (const float4*)(g_u + (b * NC + g * NCG) * NHW);
    float4* op = (float4*)(out + (b * NC + g * NCG) * NHW);
    int i4 = blockIdx.x * 256 + threadIdx.x;  // 384*256 = 98304 float4 per (b,g)
    int c = g * NCG + (i4 >> 12);
    float gam = g2[c] * rstd;
    float bet = be2[c] - mean * gam;
    float4 u = up[i4];
    op[i4] = make_float4(silu_f(fmaf(u.x, gam, bet)), silu_f(fmaf(u.y, gam, bet)),
                         silu_f(fmaf(u.z, gam, bet)), silu_f(fmaf(u.w, gam, bet)));
}

// ------------------------------- launcher -------------------------------------
extern "C" void kernel_launch(void* const* d_in, const int* in_sizes, int n_in,
                              void* d_out, int out_size) {
    const float* x = (const float*)d_in[0];
    const float* te = (const float*)d_in[1];
    const float* w1 = (const float*)d_in[2];
    const float* b1 = (const float*)d_in[3];
    const float* g1 = (const float*)d_in[4];
    const float* be1 = (const float*)d_in[5];
    const float* wt = (const float*)d_in[6];
    const float* bt = (const float*)d_in[7];
    const float* qkv_w = (const float*)d_in[8];
    const float* qkv_b = (const float*)d_in[9];
    const float* proj_w = (const float*)d_in[10];
    const float* proj_b = (const float*)d_in[11];
    const float* ga = (const float*)d_in[12];
    const float* ba = (const float*)d_in[13];
    const float* w2 = (const float*)d_in[14];
    const float* b2 = (const float*)d_in[15];
    const float* g2 = (const float*)d_in[16];
    const float* be2 = (const float*)d_in[17];
    float* out = (float*)d_out;

    cudaFuncSetAttribute(qkv_kernel, cudaFuncAttributeMaxDynamicSharedMemorySize, 61824);
    cudaFuncSetAttribute(winattn_kernel<0, 0>, cudaFuncAttributeMaxDynamicSharedMemorySize, 61824);
    cudaFuncSetAttribute(winattn_kernel<4, 1>, cudaFuncAttributeMaxDynamicSharedMemorySize, 61824);

    film_kernel<<<16, 192>>>(te, wt, bt);
    conv3x3_kernel<0><<<dim3(64, 4, 16), 192>>>(x, w1, b1);
    gn_reduce_kernel<1><<<1, 64>>>();
    gn_film_kernel<<<dim3(96, 64), 256>>>(g1, be1);
    gn_reduce_kernel<2><<<1, 64>>>();
    qkv_kernel<<<dim3(4096, 3), 256, 61824>>>(qkv_w, qkv_b, ga, ba);
    winattn_kernel<0, 0><<<dim3(256, 16), 256, 61824>>>(proj_w, proj_b);
    winattn_kernel<4, 1><<<dim3(256, 16), 256, 61824>>>(proj_w, proj_b);
    conv3x3_kernel<1><<<dim3(64, 4, 16), 192>>>(x, w2, b2);
    gn_reduce_kernel<3><<<1, 64>>>();
    gn_out_kernel<<<dim3(384, 64), 256>>>(g2, be2, out);
}

// round 7
// speedup vs baseline: 1.0087x; 1.0087x over previous
#include <cuda_runtime.h>
#include <cstdint>

#define NB 16
#define NC 96
#define NHW 16384
#define NG 4
#define NCG 24
#define NT 256
#define EPSF 1e-5f

// ---------------- scratch (no allocations allowed -> device globals) ----------
__device__ float g_u[NB * NC * NHW];          // conv outputs (reused conv1/conv2)
__device__ float g_h[NB * NC * NHW];          // residual h (post FiLM)
__device__ float g_ao[NB * NC * NHW];         // attention output accumulator (x1+x2)
__device__ float g_qkv[NB * 3 * NC * NHW];    // shared QKV tensor (both attn paths)
__device__ float g_film[NB * 2 * NC];         // silu(t_emb @ wt^T + bt)
__device__ float g_part1[NB * NG * 64 * 2];   // conv GN partials (reused)
__device__ float g_part2[NB * NG * 96 * 2];   // GN2 partials
__device__ float g_stats1[NB * NG * 2];       // (mean, rstd)
__device__ float g_stats2[NB * NG * 2];
__device__ float g_stats3[NB * NG * 2];

__device__ __forceinline__ float silu_f(float x) { return x / (1.f + __expf(-x)); }

// ---- packed f32x2 helpers (sm_103a; ptxas never emits FFMA2 from C++) --------
__device__ __forceinline__ unsigned long long pack2(float lo, float hi) {
    unsigned long long r;
    asm("mov.b64 %0, {%1, %2};" : "=l"(r) : "f"(lo), "f"(hi));
    return r;
}
__device__ __forceinline__ void fma2(unsigned long long& d, unsigned long long a,
                                     unsigned long long b) {
    asm("fma.rn.f32x2 %0, %1, %2, %0;" : "+l"(d) : "l"(a), "l"(b));
}
__device__ __forceinline__ float2 unpack2(unsigned long long v) {
    float2 r;
    asm("mov.b64 {%0, %1}, %2;" : "=f"(r.x), "=f"(r.y) : "l"(v));
    return r;
}

// ---------------- K0: FiLM MLP ------------------------------------------------
__global__ void film_kernel(const float* __restrict__ te, const float* __restrict__ wt,
                            const float* __restrict__ bt) {
    int b = blockIdx.x, o = threadIdx.x;  // 16 x 192
    const float4* e4 = (const float4*)(te + b * NT);
    const float4* w4 = (const float4*)(wt + o * NT);
    float s = bt[o];
#pragma unroll 8
    for (int k = 0; k < NT / 4; k++) {
        float4 a = e4[k], w = w4[k];
        s = fmaf(a.x, w.x, s); s = fmaf(a.y, w.y, s);
        s = fmaf(a.z, w.z, s); s = fmaf(a.w, w.w, s);
    }
    g_film[b * 192 + o] = silu_f(s);
}

// ---------------- conv3x3 (zero pad 1) + per-block GN partials ----------------
// grid: (64 row-tiles of 2 rows, 4 groups, 16 batch); block 192.
// co = tid % 24 (broadcast groups), pxg = tid / 24; pr = pxg&1, pc0 = (pxg>>1)*32.
// f32x2: adjacent output-pixel pairs. Even taps via LDS.64 from s_in;
// odd taps via LDS.64 from s_sh (one-element-shifted copy, 8B-aligned).
// SRC==0: input = src. SRC==1: input = g_h + 0.5*g_ao (fused residual+attn add)
template <int SRC>
__global__ __launch_bounds__(192) void conv3x3_kernel(const float* __restrict__ src,
                                                      const float* __restrict__ wgt,
                                                      const float* __restrict__ bias) {
    __shared__ __align__(16) float s_in[8][4][130];
    __shared__ __align__(16) float s_sh[8][4][130];   // s_sh[..][x] = s_in[..][x+1]
    __shared__ float s_w[24][73];   // stride 73: 9*co mod 32 injective -> conflict-free
    __shared__ float2 s_warp[6];
    int rt = blockIdx.x, g = blockIdx.y, b = blockIdx.z;
    int tid = threadIdx.x;
    int co = tid % 24;
    int pxg = tid / 24;
    int pr = pxg & 1, pc0 = (pxg >> 1) << 5;
    int r0 = rt << 1;
    int cog = g * NCG + co;

    unsigned long long acc2[16];
#pragma unroll
    for (int j = 0; j < 16; j++) acc2[j] = 0ull;  // (0.f,0.f)

    const float* srcB = (SRC == 0) ? (src + b * NC * NHW) : (g_h + b * NC * NHW);
    const float* aoB = g_ao + b * NC * NHW;

    for (int cc = 0; cc < 12; cc++) {
        int ci0 = cc << 3;
        for (int e = tid; e < 8 * 4 * 130; e += 192) {
            int ci = e / 520;
            int rem = e - ci * 520;
            int ry = rem / 130;
            int xx = rem - ry * 130;
            int gy = r0 - 1 + ry, gx = xx - 1;
            float v = 0.f;
            if ((unsigned)gy < 128u && (unsigned)gx < 128u) {
                int idx = (ci0 + ci) * NHW + (gy << 7) + gx;
                v = srcB[idx];
                if (SRC == 1) v = fmaf(0.5f, aoB[idx], v);
            }
            s_in[ci][ry][xx] = v;
            if (xx > 0) s_sh[ci][ry][xx - 1] = v;
        }
        for (int e = tid; e < 24 * 72; e += 192) {
            int c2 = e / 72;
            int rem = e - c2 * 72;   // rem = ci*9 + k
            s_w[c2][rem] = wgt[((g * NCG + c2) * NC + ci0) * 9 + rem];
        }
        __syncthreads();
#pragma unroll
        for (int ci = 0; ci < 8; ci++) {
#pragma unroll
            for (int dy = 0; dy < 3; dy++) {
                float wa = s_w[co][ci * 9 + dy * 3 + 0];
                float wb = s_w[co][ci * 9 + dy * 3 + 1];
                float wc = s_w[co][ci * 9 + dy * 3 + 2];
                unsigned long long wa2 = pack2(wa, wa);
                unsigned long long wb2 = pack2(wb, wb);
                unsigned long long wc2 = pack2(wc, wc);
                const unsigned long long* pe =
                    (const unsigned long long*)(&s_in[ci][pr + dy][pc0]);
                const unsigned long long* po =
                    (const unsigned long long*)(&s_sh[ci][pr + dy][pc0]);
                unsigned long long e0 = pe[0];
#pragma unroll
                for (int jp = 0; jp < 16; jp++) {
                    unsigned long long o = po[jp];
                    unsigned long long e1 = pe[jp + 1];
                    fma2(acc2[jp], e0, wa2);
                    fma2(acc2[jp], o, wb2);
                    fma2(acc2[jp], e1, wc2);
                    e0 = e1;
                }
            }
        }
        __syncthreads();
    }

    float bs = bias[cog], s = 0.f, s2 = 0.f;
    float accf[32];
#pragma unroll
    for (int jp = 0; jp < 16; jp++) {
        float2 p = unpack2(acc2[jp]);
        accf[2 * jp] = p.x + bs;
        accf[2 * jp + 1] = p.y + bs;
    }
#pragma unroll
    for (int j = 0; j < 32; j++) {
        s += accf[j];
        s2 = fmaf(accf[j], accf[j], s2);
    }
    float* op = g_u + (b * NC + cog) * NHW + ((r0 + pr) << 7) + pc0;
#pragma unroll
    for (int j = 0; j < 32; j += 4)
        *(float4*)(op + j) = make_float4(accf[j], accf[j + 1], accf[j + 2], accf[j + 3]);

    // warp shuffle tree + 6-entry serial: deterministic
#pragma unroll
    for (int off = 16; off; off >>= 1) {
        s += __shfl_xor_sync(0xffffffffu, s, off);
        s2 += __shfl_xor_sync(0xffffffffu, s2, off);
    }
    if ((tid & 31) == 0) s_warp[tid >> 5] = make_float2(s, s2);
    __syncthreads();
    if (tid == 0) {
        float a = 0.f, b2 = 0.f;
#pragma unroll
        for (int i = 0; i < 6; i++) { a += s_warp[i].x; b2 += s_warp[i].y; }
        int slot = (b * NG + g) * 64 + rt;
        g_part1[slot * 2 + 0] = a;
        g_part1[slot * 2 + 1] = b2;
    }
}

// ---------------- GN stats finalize (deterministic serial reduce) -------------
template <int WHICH>
__global__ void gn_reduce_kernel() {
    int bg = threadIdx.x;  // 64 = 16b x 4g
    const float* part = (WHICH == 2) ? g_part2 : g_part1;
    const int n = (WHICH == 2) ? 96 : 64;
    float s = 0.f, s2 = 0.f;
    for (int i = 0; i < n; i++) {
        s += part[(bg * n + i) * 2];
        s2 += part[(bg * n + i) * 2 + 1];
    }
    const float invN = 1.f / (float)(NCG * NHW);
    float mean = s * invN;
    float var = s2 * invN - mean * mean;
    if (var < 0.f) var = 0.f;
    float* st = (WHICH == 1) ? g_stats1 : (WHICH == 2) ? g_stats2 : g_stats3;
    st[bg * 2] = mean;
    st[bg * 2 + 1] = rsqrtf(var + EPSF);
}

// ---------------- K2: h = FiLM(silu(GN1(u))); accumulate GN2 partials ---------
__global__ void gn_film_kernel(const float* __restrict__ g1, const float* __restrict__ be1) {
    __shared__ float2 s_red[256];
    int bg = blockIdx.y;
    int b = bg >> 2, g = bg & 3;
    float mean = g_stats1[bg * 2], rstd = g_stats1[bg * 2 + 1];
    const float4* up = (const float4*)(g_u + (b * NC + g * NCG) * NHW);
    float4* hp = (float4*)(g_h + (b * NC + g * NCG) * NHW);
    int tid = threadIdx.x;
    float s = 0.f, s2 = 0.f;
#pragma unroll
    for (int kk = 0; kk < 4; kk++) {
        int i4 = blockIdx.x * 1024 + kk * 256 + tid;
        int c = g * NCG + (i4 >> 12);
        float gam = g1[c] * rstd;
        float bet = be1[c] - mean * gam;
        float sh = 1.f + g_film[b * 192 + c];
        float bi = g_film[b * 192 + 96 + c];
        float4 u = up[i4];
        float y0 = fmaf(silu_f(fmaf(u.x, gam, bet)), sh, bi);
        float y1 = fmaf(silu_f(fmaf(u.y, gam, bet)), sh, bi);
        float y2 = fmaf(silu_f(fmaf(u.z, gam, bet)), sh, bi);
        float y3 = fmaf(silu_f(fmaf(u.w, gam, bet)), sh, bi);
        s += y0 + y1 + y2 + y3;
        s2 = fmaf(y0, y0, s2); s2 = fmaf(y1, y1, s2);
        s2 = fmaf(y2, y2, s2); s2 = fmaf(y3, y3, s2);
        hp[i4] = make_float4(y0, y1, y2, y3);
    }
    s_red[tid] = make_float2(s, s2);
    __syncthreads();
    for (int off = 128; off > 0; off >>= 1) {
        if (tid < off) {
            s_red[tid].x += s_red[tid + off].x;
            s_red[tid].y += s_red[tid + off].y;
        }
        __syncthreads();
    }
    if (tid == 0) {
        int slot = bg * 96 + blockIdx.x;
        g_part2[slot * 2 + 0] = s_red[0].x;
        g_part2[slot * 2 + 1] = s_red[0].y;
    }
}

// ---------------- K3: qkv = W_qkv @ GN2(h), shared by both attn paths ---------
// grid: (4096 px-tiles of 64, 3 row-tiles of 96). block 256 = 16 rowg x 16 lg
__global__ __launch_bounds__(256) void qkv_kernel(const float* __restrict__ qw,
                                                  const float* __restrict__ qb,
                                                  const float* __restrict__ ga,
                                                  const float* __restrict__ ba) {
    extern __shared__ float sm[];
    float* s_hn = sm;           // 96 x 64
    float* s_w = sm + 6144;     // 96 x 97 (padded)
    int pxt = blockIdx.x, rt = blockIdx.y;
    int b = pxt >> 8, sp0 = (pxt & 255) << 6;
    int tid = threadIdx.x;

    for (int e = tid; e < 1536; e += 256) {  // float4 elements of 96x64
        int c = e >> 4;
        int grp = c / 24;
        float mean = g_stats2[(b * NG + grp) * 2];
        float rstd = g_stats2[(b * NG + grp) * 2 + 1];
        float gam = ga[c] * rstd;
        float bet = ba[c] - mean * gam;
        float4 v = *(const float4*)(g_h + (b * NC + c) * NHW + sp0 + ((e & 15) << 2));
        v.x = fmaf(v.x, gam, bet); v.y = fmaf(v.y, gam, bet);
        v.z = fmaf(v.z, gam, bet); v.w = fmaf(v.w, gam, bet);
        ((float4*)s_hn)[e] = v;
    }
    const float* qwB = qw + rt * 96 * 96;
    for (int e = tid; e < 9216; e += 256) {
        int row = e / 96, col = e - row * 96;
        s_w[row * 97 + col] = qwB[e];
    }
    __syncthreads();

    int lg = tid & 15, rowg = tid >> 4;
    unsigned long long acc2[6][2];
#pragma unroll
    for (int r = 0; r < 6; r++) { acc2[r][0] = 0ull; acc2[r][1] = 0ull; }

#pragma unroll 4
    for (int c = 0; c < 96; c++) {
        const unsigned long long* hv =
            (const unsigned long long*)(s_hn + (c << 6) + (lg << 2));
        unsigned long long h01 = hv[0], h23 = hv[1];
#pragma unroll
        for (int rr = 0; rr < 6; rr++) {
            float wv = s_w[(rowg * 6 + rr) * 97 + c];
            unsigned long long wv2 = pack2(wv, wv);
            fma2(acc2[rr][0], h01, wv2);
            fma2(acc2[rr][1], h23, wv2);
        }
    }
#pragma unroll
    for (int rr = 0; rr < 6; rr++) {
        int row = rt * 96 + rowg * 6 + rr;
        float bb = qb[row];
        float2 p01 = unpack2(acc2[rr][0]);
        float2 p23 = unpack2(acc2[rr][1]);
        *(float4*)(g_qkv + (b * 288 + row) * NHW + sp0 + (lg << 2)) =
            make_float4(p01.x + bb, p01.y + bb, p23.x + bb, p23.y + bb);
    }
}

// ---------------- K4: window attention (6x6 channel-attn, 16 heads) + proj ----
// block = one 8x8 window. 16 teams of 16 lanes, 4 px per lane.
// q/k/v loaded straight from global into registers; proj with f32x2.
// SHIFT=0 writes g_ao; SHIFT=4 (wraparound roll) accumulates.
template <int SHIFT, int ACC>
__global__ __launch_bounds__(256) void winattn_kernel(const float* __restrict__ pw,
                                                      const float* __restrict__ pb) {
    extern __shared__ float sm[];
    float* s_out = sm;            // 96 x 64
    float* s_pw = sm + 6144;      // 96 x 97 (padded)
    int w = blockIdx.x, b = blockIdx.y;
    int wi = w >> 4, wj = w & 15;
    int r0 = wi * 8 + SHIFT, c0 = wj * 8 + SHIFT;
    int tid = threadIdx.x;
    int team = tid >> 4, ln = tid & 15, l0 = ln << 2;

    // stage proj weights (no dependency; overlaps with global q/k/v loads)
    for (int e = tid; e < 9216; e += 256) {
        int row = e / 96, col = e - row * 96;
        s_pw[row * 97 + col] = pw[e];
    }

    // this lane's 4 pixels (one half-row of the window; never splits at wrap)
    int gr = (r0 + (l0 >> 3)) & 127;
    int gc = (c0 + (l0 & 7)) & 127;
    const float* qkvB = g_qkv + (size_t)b * 288 * NHW + (gr << 7) + gc;

    float q[6][4], k[6][4], v[6][4];
#pragma unroll
    for (int d = 0; d < 6; d++) {
        float4 t;
        t = *(const float4*)(qkvB + (team * 6 + d) * NHW);
        q[d][0] = t.x; q[d][1] = t.y; q[d][2] = t.z; q[d][3] = t.w;
        t = *(const float4*)(qkvB + (96 + team * 6 + d) * NHW);
        k[d][0] = t.x; k[d][1] = t.y; k[d][2] = t.z; k[d][3] = t.w;
        t = *(const float4*)(qkvB + (192 + team * 6 + d) * NHW);
        v[d][0] = t.x; v[d][1] = t.y; v[d][2] = t.z; v[d][3] = t.w;
    }
    float S[6][6];
#pragma unroll
    for (int d = 0; d < 6; d++)
#pragma unroll
        for (int e = 0; e < 6; e++) {
            float ps = q[d][0] * k[e][0];
            ps = fmaf(q[d][1], k[e][1], ps);
            ps = fmaf(q[d][2], k[e][2], ps);
            ps = fmaf(q[d][3], k[e][3], ps);
            S[d][e] = ps;
        }
#pragma unroll
    for (int off = 8; off > 0; off >>= 1)
#pragma unroll
        for (int d = 0; d < 6; d++)
#pragma unroll
            for (int e = 0; e < 6; e++)
                S[d][e] += __shfl_xor_sync(0xffffffffu, S[d][e], off);

    const float scl = 0.4082482904638631f;  // 6^-0.5
#pragma unroll
    for (int d = 0; d < 6; d++) {
        float m = S[d][0];
#pragma unroll
        for (int e = 1; e < 6; e++) m = fmaxf(m, S[d][e]);
        float sum = 0.f;
#pragma unroll
        for (int e = 0; e < 6; e++) {
            S[d][e] = __expf((S[d][e] - m) * scl);
            sum += S[d][e];
        }
        float inv = 1.f / sum;
        float o[4];
#pragma unroll
        for (int j = 0; j < 4; j++) {
            float t = S[d][0] * v[0][j];
            t = fmaf(S[d][1], v[1][j], t);
            t = fmaf(S[d][2], v[2][j], t);
            t = fmaf(S[d][3], v[3][j], t);
            t = fmaf(S[d][4], v[4][j], t);
            t = fmaf(S[d][5], v[5][j], t);
            o[j] = t * inv;
        }
        *(float4*)(s_out + ((team * 6 + d) << 6) + l0) =
            make_float4(o[0], o[1], o[2], o[3]);
    }
    __syncthreads();  // s_out + s_pw complete

    unsigned long long pa2[6][2];
#pragma unroll
    for (int m = 0; m < 6; m++) { pa2[m][0] = 0ull; pa2[m][1] = 0ull; }
#pragma unroll 4
    for (int c = 0; c < 96; c++) {
        const unsigned long long* ov =
            (const unsigned long long*)(s_out + (c << 6) + l0);
        unsigned long long o01 = ov[0], o23 = ov[1];
#pragma unroll
        for (int m = 0; m < 6; m++) {
            float wv = s_pw[(team * 6 + m) * 97 + c];
            unsigned long long wv2 = pack2(wv, wv);
            fma2(pa2[m][0], o01, wv2);
            fma2(pa2[m][1], o23, wv2);
        }
    }
    float* outp = g_ao + (size_t)b * NC * NHW + (gr << 7) + gc;
#pragma unroll
    for (int m = 0; m < 6; m++) {
        int co = team * 6 + m;
        float bb = pb[co];
        float2 p01 = unpack2(pa2[m][0]);
        float2 p23 = unpack2(pa2[m][1]);
        float4 val = make_float4(p01.x + bb, p01.y + bb, p23.x + bb, p23.y + bb);
        float* p = outp + co * NHW;
        if (ACC) {
            float4 old = *(float4*)p;
            val.x += old.x; val.y += old.y; val.z += old.z; val.w += old.w;
        }
        *(float4*)p = val;
    }
}

// ---------------- K6: out = silu(GN3(u)) --------------------------------------
__global__ void gn_out_kernel(const float* __restrict__ g2, const float* __restrict__ be2,
                              float* __restrict__ out) {
    int bg = blockIdx.y;
    int b = bg >> 2, g = bg & 3;
    float mean = g_stats3[bg * 2], rstd = g_stats3[bg * 2 + 1];
    const float4* up = (const float4*)(g_u + (b * NC + g * NCG) * NHW);
    float4* op = (float4*)(out + (b * NC + g * NCG) * NHW);
    int i4 = blockIdx.x * 256 + threadIdx.x;  // 384*256 = 98304 float4 per (b,g)
    int c = g * NCG + (i4 >> 12);
    float gam = g2[c] * rstd;
    float bet = be2[c] - mean * gam;
    float4 u = up[i4];
    op[i4] = make_float4(silu_f(fmaf(u.x, gam, bet)), silu_f(fmaf(u.y, gam, bet)),
                         silu_f(fmaf(u.z, gam, bet)), silu_f(fmaf(u.w, gam, bet)));
}

// ------------------------------- launcher -------------------------------------
extern "C" void kernel_launch(void* const* d_in, const int* in_sizes, int n_in,
                              void* d_out, int out_size) {
    const float* x = (const float*)d_in[0];
    const float* te = (const float*)d_in[1];
    const float* w1 = (const float*)d_in[2];
    const float* b1 = (const float*)d_in[3];
    const float* g1 = (const float*)d_in[4];
    const float* be1 = (const float*)d_in[5];
    const float* wt = (const float*)d_in[6];
    const float* bt = (const float*)d_in[7];
    const float* qkv_w = (const float*)d_in[8];
    const float* qkv_b = (const float*)d_in[9];
    const float* proj_w = (const float*)d_in[10];
    const float* proj_b = (const float*)d_in[11];
    const float* ga = (const float*)d_in[12];
    const float* ba = (const float*)d_in[13];
    const float* w2 = (const float*)d_in[14];
    const float* b2 = (const float*)d_in[15];
    const float* g2 = (const float*)d_in[16];
    const float* be2 = (const float*)d_in[17];
    float* out = (float*)d_out;

    cudaFuncSetAttribute(qkv_kernel, cudaFuncAttributeMaxDynamicSharedMemorySize, 61824);
    cudaFuncSetAttribute(winattn_kernel<0, 0>, cudaFuncAttributeMaxDynamicSharedMemorySize, 61824);
    cudaFuncSetAttribute(winattn_kernel<4, 1>, cudaFuncAttributeMaxDynamicSharedMemorySize, 61824);

    film_kernel<<<16, 192>>>(te, wt, bt);
    conv3x3_kernel<0><<<dim3(64, 4, 16), 192>>>(x, w1, b1);
    gn_reduce_kernel<1><<<1, 64>>>();
    gn_film_kernel<<<dim3(96, 64), 256>>>(g1, be1);
    gn_reduce_kernel<2><<<1, 64>>>();
    qkv_kernel<<<dim3(4096, 3), 256, 61824>>>(qkv_w, qkv_b, ga, ba);
    winattn_kernel<0, 0><<<dim3(256, 16), 256, 61824>>>(proj_w, proj_b);
    winattn_kernel<4, 1><<<dim3(256, 16), 256, 61824>>>(proj_w, proj_b);
    conv3x3_kernel<1><<<dim3(64, 4, 16), 192>>>(x, w2, b2);
    gn_reduce_kernel<3><<<1, 64>>>();
    gn_out_kernel<<<dim3(384, 64), 256>>>(g2, be2, out);
}

// round 8
// speedup vs baseline: 1.0114x; 1.0027x over previous
#include <cuda_runtime.h>
#include <cstdint>

#define NB 16
#define NC 96
#define NHW 16384
#define NG 4
#define NCG 24
#define NT 256
#define EPSF 1e-5f

// ---------------- scratch (no allocations allowed -> device globals) ----------
__device__ float g_u[NB * NC * NHW];          // conv outputs (reused conv1/conv2)
__device__ float g_h[NB * NC * NHW];          // residual h (post FiLM)
__device__ float g_ao[NB * NC * NHW];         // attention output accumulator (x1+x2)
__device__ float g_qkv[NB * 3 * NC * NHW];    // shared QKV tensor (both attn paths)
__device__ float g_film[NB * 2 * NC];         // silu(t_emb @ wt^T + bt)
__device__ float g_part1[NB * NG * 64 * 2];   // conv GN partials (reused)
__device__ float g_part2[NB * NG * 96 * 2];   // GN2 partials
__device__ float g_stats1[NB * NG * 2];       // (mean, rstd)
__device__ float g_stats2[NB * NG * 2];
__device__ float g_stats3[NB * NG * 2];

__device__ __forceinline__ float silu_f(float x) { return x / (1.f + __expf(-x)); }

// ---- packed f32x2 helpers (sm_103a; ptxas never emits FFMA2 from C++) --------
__device__ __forceinline__ unsigned long long pack2(float lo, float hi) {
    unsigned long long r;
    asm("mov.b64 %0, {%1, %2};" : "=l"(r) : "f"(lo), "f"(hi));
    return r;
}
__device__ __forceinline__ void fma2(unsigned long long& d, unsigned long long a,
                                     unsigned long long b) {
    asm("fma.rn.f32x2 %0, %1, %2, %0;" : "+l"(d) : "l"(a), "l"(b));
}
__device__ __forceinline__ float2 unpack2(unsigned long long v) {
    float2 r;
    asm("mov.b64 {%0, %1}, %2;" : "=f"(r.x), "=f"(r.y) : "l"(v));
    return r;
}

// ---------------- K0: FiLM MLP ------------------------------------------------
__global__ void film_kernel(const float* __restrict__ te, const float* __restrict__ wt,
                            const float* __restrict__ bt) {
    int b = blockIdx.x, o = threadIdx.x;  // 16 x 192
    const float4* e4 = (const float4*)(te + b * NT);
    const float4* w4 = (const float4*)(wt + o * NT);
    float s = bt[o];
#pragma unroll 8
    for (int k = 0; k < NT / 4; k++) {
        float4 a = e4[k], w = w4[k];
        s = fmaf(a.x, w.x, s); s = fmaf(a.y, w.y, s);
        s = fmaf(a.z, w.z, s); s = fmaf(a.w, w.w, s);
    }
    g_film[b * 192 + o] = silu_f(s);
}

// ---------------- conv3x3 (zero pad 1) + per-block GN partials ----------------
// grid: (64 row-tiles of 2 rows, 4 groups, 16 batch); block 192.
// co = tid % 24 (broadcast groups), pxg = tid / 24; pr = pxg&1, pc0 = (pxg>>1)*32.
// f32x2: adjacent output-pixel pairs. Even taps via LDS.64 from s_in;
// odd taps via LDS.64 from s_sh (one-element-shifted copy, 8B-aligned).
// SRC==0: input = src. SRC==1: input = g_h + 0.5*g_ao (fused residual+attn add)
template <int SRC>
__global__ __launch_bounds__(192) void conv3x3_kernel(const float* __restrict__ src,
                                                      const float* __restrict__ wgt,
                                                      const float* __restrict__ bias) {
    __shared__ __align__(16) float s_in[8][4][130];
    __shared__ __align__(16) float s_sh[8][4][130];   // s_sh[..][x] = s_in[..][x+1]
    __shared__ float s_w[24][73];   // stride 73: 9*co mod 32 injective -> conflict-free
    __shared__ float2 s_warp[6];
    int rt = blockIdx.x, g = blockIdx.y, b = blockIdx.z;
    int tid = threadIdx.x;
    int co = tid % 24;
    int pxg = tid / 24;
    int pr = pxg & 1, pc0 = (pxg >> 1) << 5;
    int r0 = rt << 1;
    int cog = g * NCG + co;

    unsigned long long acc2[16];
#pragma unroll
    for (int j = 0; j < 16; j++) acc2[j] = 0ull;  // (0.f,0.f)

    const float* srcB = (SRC == 0) ? (src + b * NC * NHW) : (g_h + b * NC * NHW);
    const float* aoB = g_ao + b * NC * NHW;

    for (int cc = 0; cc < 12; cc++) {
        int ci0 = cc << 3;
        for (int e = tid; e < 8 * 4 * 130; e += 192) {
            int ci = e / 520;
            int rem = e - ci * 520;
            int ry = rem / 130;
            int xx = rem - ry * 130;
            int gy = r0 - 1 + ry, gx = xx - 1;
            float v = 0.f;
            if ((unsigned)gy < 128u && (unsigned)gx < 128u) {
                int idx = (ci0 + ci) * NHW + (gy << 7) + gx;
                v = srcB[idx];
                if (SRC == 1) v = fmaf(0.5f, aoB[idx], v);
            }
            s_in[ci][ry][xx] = v;
            if (xx > 0) s_sh[ci][ry][xx - 1] = v;
        }
        for (int e = tid; e < 24 * 72; e += 192) {
            int c2 = e / 72;
            int rem = e - c2 * 72;   // rem = ci*9 + k
            s_w[c2][rem] = wgt[((g * NCG + c2) * NC + ci0) * 9 + rem];
        }
        __syncthreads();
#pragma unroll
        for (int ci = 0; ci < 8; ci++) {
#pragma unroll
            for (int dy = 0; dy < 3; dy++) {
                float wa = s_w[co][ci * 9 + dy * 3 + 0];
                float wb = s_w[co][ci * 9 + dy * 3 + 1];
                float wc = s_w[co][ci * 9 + dy * 3 + 2];
                unsigned long long wa2 = pack2(wa, wa);
                unsigned long long wb2 = pack2(wb, wb);
                unsigned long long wc2 = pack2(wc, wc);
                const unsigned long long* pe =
                    (const unsigned long long*)(&s_in[ci][pr + dy][pc0]);
                const unsigned long long* po =
                    (const unsigned long long*)(&s_sh[ci][pr + dy][pc0]);
                unsigned long long e0 = pe[0];
#pragma unroll
                for (int jp = 0; jp < 16; jp++) {
                    unsigned long long o = po[jp];
                    unsigned long long e1 = pe[jp + 1];
                    fma2(acc2[jp], e0, wa2);
                    fma2(acc2[jp], o, wb2);
                    fma2(acc2[jp], e1, wc2);
                    e0 = e1;
                }
            }
        }
        __syncthreads();
    }

    float bs = bias[cog], s = 0.f, s2 = 0.f;
    float accf[32];
#pragma unroll
    for (int jp = 0; jp < 16; jp++) {
        float2 p = unpack2(acc2[jp]);
        accf[2 * jp] = p.x + bs;
        accf[2 * jp + 1] = p.y + bs;
    }
#pragma unroll
    for (int j = 0; j < 32; j++) {
        s += accf[j];
        s2 = fmaf(accf[j], accf[j], s2);
    }
    float* op = g_u + (b * NC + cog) * NHW + ((r0 + pr) << 7) + pc0;
#pragma unroll
    for (int j = 0; j < 32; j += 4)
        *(float4*)(op + j) = make_float4(accf[j], accf[j + 1], accf[j + 2], accf[j + 3]);

    // warp shuffle tree + 6-entry serial: deterministic
#pragma unroll
    for (int off = 16; off; off >>= 1) {
        s += __shfl_xor_sync(0xffffffffu, s, off);
        s2 += __shfl_xor_sync(0xffffffffu, s2, off);
    }
    if ((tid & 31) == 0) s_warp[tid >> 5] = make_float2(s, s2);
    __syncthreads();
    if (tid == 0) {
        float a = 0.f, b2 = 0.f;
#pragma unroll
        for (int i = 0; i < 6; i++) { a += s_warp[i].x; b2 += s_warp[i].y; }
        int slot = (b * NG + g) * 64 + rt;
        g_part1[slot * 2 + 0] = a;
        g_part1[slot * 2 + 1] = b2;
    }
}

// ---------------- GN stats finalize (deterministic serial reduce) -------------
template <int WHICH>
__global__ void gn_reduce_kernel() {
    int bg = threadIdx.x;  // 64 = 16b x 4g
    const float* part = (WHICH == 2) ? g_part2 : g_part1;
    const int n = (WHICH == 2) ? 96 : 64;
    float s = 0.f, s2 = 0.f;
    for (int i = 0; i < n; i++) {
        s += part[(bg * n + i) * 2];
        s2 += part[(bg * n + i) * 2 + 1];
    }
    const float invN = 1.f / (float)(NCG * NHW);
    float mean = s * invN;
    float var = s2 * invN - mean * mean;
    if (var < 0.f) var = 0.f;
    float* st = (WHICH == 1) ? g_stats1 : (WHICH == 2) ? g_stats2 : g_stats3;
    st[bg * 2] = mean;
    st[bg * 2 + 1] = rsqrtf(var + EPSF);
}

// ---------------- K2: h = FiLM(silu(GN1(u))); accumulate GN2 partials ---------
__global__ void gn_film_kernel(const float* __restrict__ g1, const float* __restrict__ be1) {
    __shared__ float2 s_red[256];
    int bg = blockIdx.y;
    int b = bg >> 2, g = bg & 3;
    float mean = g_stats1[bg * 2], rstd = g_stats1[bg * 2 + 1];
    const float4* up = (const float4*)(g_u + (b * NC + g * NCG) * NHW);
    float4* hp = (float4*)(g_h + (b * NC + g * NCG) * NHW);
    int tid = threadIdx.x;
    float s = 0.f, s2 = 0.f;
#pragma unroll
    for (int kk = 0; kk < 4; kk++) {
        int i4 = blockIdx.x * 1024 + kk * 256 + tid;
        int c = g * NCG + (i4 >> 12);
        float gam = g1[c] * rstd;
        float bet = be1[c] - mean * gam;
        float sh = 1.f + g_film[b * 192 + c];
        float bi = g_film[b * 192 + 96 + c];
        float4 u = up[i4];
        float y0 = fmaf(silu_f(fmaf(u.x, gam, bet)), sh, bi);
        float y1 = fmaf(silu_f(fmaf(u.y, gam, bet)), sh, bi);
        float y2 = fmaf(silu_f(fmaf(u.z, gam, bet)), sh, bi);
        float y3 = fmaf(silu_f(fmaf(u.w, gam, bet)), sh, bi);
        s += y0 + y1 + y2 + y3;
        s2 = fmaf(y0, y0, s2); s2 = fmaf(y1, y1, s2);
        s2 = fmaf(y2, y2, s2); s2 = fmaf(y3, y3, s2);
        hp[i4] = make_float4(y0, y1, y2, y3);
    }
    s_red[tid] = make_float2(s, s2);
    __syncthreads();
    for (int off = 128; off > 0; off >>= 1) {
        if (tid < off) {
            s_red[tid].x += s_red[tid + off].x;
            s_red[tid].y += s_red[tid + off].y;
        }
        __syncthreads();
    }
    if (tid == 0) {
        int slot = bg * 96 + blockIdx.x;
        g_part2[slot * 2 + 0] = s_red[0].x;
        g_part2[slot * 2 + 1] = s_red[0].y;
    }
}

// ---------------- K3: qkv = W_qkv @ GN2(h), shared by both attn paths ---------
// grid: (4096 px-tiles of 64, 3 row-tiles of 96). block 256 = 16 rowg x 16 lg
__global__ __launch_bounds__(256) void qkv_kernel(const float* __restrict__ qw,
                                                  const float* __restrict__ qb,
                                                  const float* __restrict__ ga,
                                                  const float* __restrict__ ba) {
    extern __shared__ float sm[];
    float* s_hn = sm;           // 96 x 64
    float* s_w = sm + 6144;     // 96 x 97 (padded)
    int pxt = blockIdx.x, rt = blockIdx.y;
    int b = pxt >> 8, sp0 = (pxt & 255) << 6;
    int tid = threadIdx.x;

    for (int e = tid; e < 1536; e += 256) {  // float4 elements of 96x64
        int c = e >> 4;
        int grp = c / 24;
        float mean = g_stats2[(b * NG + grp) * 2];
        float rstd = g_stats2[(b * NG + grp) * 2 + 1];
        float gam = ga[c] * rstd;
        float bet = ba[c] - mean * gam;
        float4 v = *(const float4*)(g_h + (b * NC + c) * NHW + sp0 + ((e & 15) << 2));
        v.x = fmaf(v.x, gam, bet); v.y = fmaf(v.y, gam, bet);
        v.z = fmaf(v.z, gam, bet); v.w = fmaf(v.w, gam, bet);
        ((float4*)s_hn)[e] = v;
    }
    const float* qwB = qw + rt * 96 * 96;
    for (int e = tid; e < 9216; e += 256) {
        int row = e / 96, col = e - row * 96;
        s_w[row * 97 + col] = qwB[e];
    }
    __syncthreads();

    int lg = tid & 15, rowg = tid >> 4;
    unsigned long long acc2[6][2];
#pragma unroll
    for (int r = 0; r < 6; r++) { acc2[r][0] = 0ull; acc2[r][1] = 0ull; }

#pragma unroll 4
    for (int c = 0; c < 96; c++) {
        const unsigned long long* hv =
            (const unsigned long long*)(s_hn + (c << 6) + (lg << 2));
        unsigned long long h01 = hv[0], h23 = hv[1];
#pragma unroll
        for (int rr = 0; rr < 6; rr++) {
            float wv = s_w[(rowg * 6 + rr) * 97 + c];
            unsigned long long wv2 = pack2(wv, wv);
            fma2(acc2[rr][0], h01, wv2);
            fma2(acc2[rr][1], h23, wv2);
        }
    }
#pragma unroll
    for (int rr = 0; rr < 6; rr++) {
        int row = rt * 96 + rowg * 6 + rr;
        float bb = qb[row];
        float2 p01 = unpack2(acc2[rr][0]);
        float2 p23 = unpack2(acc2[rr][1]);
        *(float4*)(g_qkv + (b * 288 + row) * NHW + sp0 + (lg << 2)) =
            make_float4(p01.x + bb, p01.y + bb, p23.x + bb, p23.y + bb);
    }
}

// ---------------- K4: window attention (6x6 channel-attn, 16 heads) + proj ----
// block = one 8x8 window. 16 teams of 16 lanes, 4 px per lane.
// q/k/v loaded straight from global into registers; proj with f32x2.
// SHIFT=0 writes g_ao; SHIFT=4 (wraparound roll) accumulates.
template <int SHIFT, int ACC>
__global__ __launch_bounds__(256) void winattn_kernel(const float* __restrict__ pw,
                                                      const float* __restrict__ pb) {
    extern __shared__ float sm[];
    float* s_out = sm;            // 96 x 64
    float* s_pw = sm + 6144;      // 96 x 97 (padded)
    int w = blockIdx.x, b = blockIdx.y;
    int wi = w >> 4, wj = w & 15;
    int r0 = wi * 8 + SHIFT, c0 = wj * 8 + SHIFT;
    int tid = threadIdx.x;
    int team = tid >> 4, ln = tid & 15, l0 = ln << 2;

    // stage proj weights (no dependency; overlaps with global q/k/v loads)
    for (int e = tid; e < 9216; e += 256) {
        int row = e / 96, col = e - row * 96;
        s_pw[row * 97 + col] = pw[e];
    }

    // this lane's 4 pixels (one half-row of the window; never splits at wrap)
    int gr = (r0 + (l0 >> 3)) & 127;
    int gc = (c0 + (l0 & 7)) & 127;
    const float* qkvB = g_qkv + (size_t)b * 288 * NHW + (gr << 7) + gc;

    float q[6][4], k[6][4], v[6][4];
#pragma unroll
    for (int d = 0; d < 6; d++) {
        float4 t;
        t = *(const float4*)(qkvB + (team * 6 + d) * NHW);
        q[d][0] = t.x; q[d][1] = t.y; q[d][2] = t.z; q[d][3] = t.w;
        t = *(const float4*)(qkvB + (96 + team * 6 + d) * NHW);
        k[d][0] = t.x; k[d][1] = t.y; k[d][2] = t.z; k[d][3] = t.w;
        t = *(const float4*)(qkvB + (192 + team * 6 + d) * NHW);
        v[d][0] = t.x; v[d][1] = t.y; v[d][2] = t.z; v[d][3] = t.w;
    }
    float S[6][6];
#pragma unroll
    for (int d = 0; d < 6; d++)
#pragma unroll
        for (int e = 0; e < 6; e++) {
            float ps = q[d][0] * k[e][0];
            ps = fmaf(q[d][1], k[e][1], ps);
            ps = fmaf(q[d][2], k[e][2], ps);
            ps = fmaf(q[d][3], k[e][3], ps);
            S[d][e] = ps;
        }
#pragma unroll
    for (int off = 8; off > 0; off >>= 1)
#pragma unroll
        for (int d = 0; d < 6; d++)
#pragma unroll
            for (int e = 0; e < 6; e++)
                S[d][e] += __shfl_xor_sync(0xffffffffu, S[d][e], off);

    const float scl = 0.4082482904638631f;  // 6^-0.5
#pragma unroll
    for (int d = 0; d < 6; d++) {
        float m = S[d][0];
#pragma unroll
        for (int e = 1; e < 6; e++) m = fmaxf(m, S[d][e]);
        float sum = 0.f;
#pragma unroll
        for (int e = 0; e < 6; e++) {
            S[d][e] = __expf((S[d][e] - m) * scl);
            sum += S[d][e];
        }
        float inv = 1.f / sum;
        float o[4];
#pragma unroll
        for (int j = 0; j < 4; j++) {
            float t = S[d][0] * v[0][j];
            t = fmaf(S[d][1], v[1][j], t);
            t = fmaf(S[d][2], v[2][j], t);
            t = fmaf(S[d][3], v[3][j], t);
            t = fmaf(S[d][4], v[4][j], t);
            t = fmaf(S[d][5], v[5][j], t);
            o[j] = t * inv;
        }
        *(float4*)(s_out + ((team * 6 + d) << 6) + l0) =
            make_float4(o[0], o[1], o[2], o[3]);
    }
    __syncthreads();  // s_out + s_pw complete

    unsigned long long pa2[6][2];
#pragma unroll
    for (int m = 0; m < 6; m++) { pa2[m][0] = 0ull; pa2[m][1] = 0ull; }
#pragma unroll 4
    for (int c = 0; c < 96; c++) {
        const unsigned long long* ov =
            (const unsigned long long*)(s_out + (c << 6) + l0);
        unsigned long long o01 = ov[0], o23 = ov[1];
#pragma unroll
        for (int m = 0; m < 6; m++) {
            float wv = s_pw[(team * 6 + m) * 97 + c];
            unsigned long long wv2 = pack2(wv, wv);
            fma2(pa2[m][0], o01, wv2);
            fma2(pa2[m][1], o23, wv2);
        }
    }
    float* outp = g_ao + (size_t)b * NC * NHW + (gr << 7) + gc;
#pragma unroll
    for (int m = 0; m < 6; m++) {
        int co = team * 6 + m;
        float bb = pb[co];
        float2 p01 = unpack2(pa2[m][0]);
        float2 p23 = unpack2(pa2[m][1]);
        float4 val = make_float4(p01.x + bb, p01.y + bb, p23.x + bb, p23.y + bb);
        float* p = outp + co * NHW;
        if (ACC) {
            float4 old = *(float4*)p;
            val.x += old.x; val.y += old.y; val.z += old.z; val.w += old.w;
        }
        *(float4*)p = val;
    }
}

// ---------------- K6: out = silu(GN3(u)) --------------------------------------
__global__ void gn_out_kernel(const float* __restrict__ g2, const float* __restrict__ be2,
                              float* __restrict__ out) {
    int bg = blockIdx.y;
    int b = bg >> 2, g = bg & 3;
    float mean = g_stats3[bg * 2], rstd = g_stats3[bg * 2 + 1];
    const float4* up = (const float4*)(g_u + (b * NC + g * NCG) * NHW);
    float4* op = (float4*)(out + (b * NC + g * NCG) * NHW);
    int i4 = blockIdx.x * 256 + threadIdx.x;  // 384*256 = 98304 float4 per (b,g)
    int c = g * NCG + (i4 >> 12);
    float gam = g2[c] * rstd;
    float bet = be2[c] - mean * gam;
    float4 u = up[i4];
    op[i4] = make_float4(silu_f(fmaf(u.x, gam, bet)), silu_f(fmaf(u.y, gam, bet)),
                         silu_f(fmaf(u.z, gam, bet)), silu_f(fmaf(u.w, gam, bet)));
}

// ------------------------------- launcher -------------------------------------
extern "C" void kernel_launch(void* const* d_in, const int* in_sizes, int n_in,
                              void* d_out, int out_size) {
    const float* x = (const float*)d_in[0];
    const float* te = (const float*)d_in[1];
    const float* w1 = (const float*)d_in[2];
    const float* b1 = (const float*)d_in[3];
    const float* g1 = (const float*)d_in[4];
    const float* be1 = (const float*)d_in[5];
    const float* wt = (const float*)d_in[6];
    const float* bt = (const float*)d_in[7];
    const float* qkv_w = (const float*)d_in[8];
    const float* qkv_b = (const float*)d_in[9];
    const float* proj_w = (const float*)d_in[10];
    const float* proj_b = (const float*)d_in[11];
    const float* ga = (const float*)d_in[12];
    const float* ba = (const float*)d_in[13];
    const float* w2 = (const float*)d_in[14];
    const float* b2 = (const float*)d_in[15];
    const float* g2 = (const float*)d_in[16];
    const float* be2 = (const float*)d_in[17];
    float* out = (float*)d_out;

    cudaFuncSetAttribute(qkv_kernel, cudaFuncAttributeMaxDynamicSharedMemorySize, 61824);
    cudaFuncSetAttribute(winattn_kernel<0, 0>, cudaFuncAttributeMaxDynamicSharedMemorySize, 61824);
    cudaFuncSetAttribute(winattn_kernel<4, 1>, cudaFuncAttributeMaxDynamicSharedMemorySize, 61824);

    film_kernel<<<16, 192>>>(te, wt, bt);
    conv3x3_kernel<0><<<dim3(64, 4, 16), 192>>>(x, w1, b1);
    gn_reduce_kernel<1><<<1, 64>>>();
    gn_film_kernel<<<dim3(96, 64), 256>>>(g1, be1);
    gn_reduce_kernel<2><<<1, 64>>>();
    qkv_kernel<<<dim3(4096, 3), 256, 61824>>>(qkv_w, qkv_b, ga, ba);
    winattn_kernel<0, 0><<<dim3(256, 16), 256, 61824>>>(proj_w, proj_b);
    winattn_kernel<4, 1><<<dim3(256, 16), 256, 61824>>>(proj_w, proj_b);
    conv3x3_kernel<1><<<dim3(64, 4, 16), 192>>>(x, w2, b2);
    gn_reduce_kernel<3><<<1, 64>>>();
    gn_out_kernel<<<dim3(384, 64), 256>>>(g2, be2, out);
}